// round 7
// baseline (speedup 1.0000x reference)
#include <cuda_runtime.h>
#include <math.h>
#include <stdint.h>

#define SS 512
#define BB 64
#define II 1024
#define HH 1024
#define SB (SS*BB)

// ---------------- scratch (static device globals; no allocation) -------------
__device__ float g_XP[4ULL * SB * HH];          // input projections [4][S*B][H]
__device__ float g_Hall[(size_t)SB * HH];       // h_t row-major [S][B][H]
__device__ float g_HTp[2][HH * BB];             // h transposed+pair-packed, ping-pong
__device__ float g_Wpk[128ULL * 128 * 32 * 8];  // packed recurrent weights
__device__ unsigned g_bar;                       // grid barrier (monotonic)

// ---------------- helpers ----------------------------------------------------
__device__ __forceinline__ float f2tf32(float f) {
    uint32_t r;
    asm("cvt.rna.tf32.f32 %0, %1;" : "=r"(r) : "f"(f));
    return __uint_as_float(r);
}

__device__ __forceinline__ void mma_tf32(float c[4], const uint32_t a[4], const uint32_t b[2]) {
    asm volatile(
        "mma.sync.aligned.m16n8k8.row.col.f32.tf32.tf32.f32 "
        "{%0,%1,%2,%3}, {%4,%5,%6,%7}, {%8,%9}, {%0,%1,%2,%3};"
        : "+f"(c[0]), "+f"(c[1]), "+f"(c[2]), "+f"(c[3])
        : "r"(a[0]), "r"(a[1]), "r"(a[2]), "r"(a[3]), "r"(b[0]), "r"(b[1]));
}

__device__ __forceinline__ void cp_async16(uint32_t dst_smem, const void* src) {
    asm volatile("cp.async.cg.shared.global [%0], [%1], 16;" :: "r"(dst_smem), "l"(src));
}
__device__ __forceinline__ void cp_commit() { asm volatile("cp.async.commit_group;"); }
template<int N> __device__ __forceinline__ void cp_wait() {
    asm volatile("cp.async.wait_group %0;" :: "n"(N));
}

// ---------------- init -------------------------------------------------------
__global__ void init_state_kernel() {
    int idx = blockIdx.x * blockDim.x + threadIdx.x;
    if (idx < BB * HH) g_HTp[0][idx] = 0.0f;
    if (idx == 0) g_bar = 0u;
}

// ---------------- weight repack ----------------------------------------------
__global__ __launch_bounds__(256) void repack_w(
    const float* __restrict__ Wi, const float* __restrict__ Wf,
    const float* __restrict__ Wc, const float* __restrict__ Wo)
{
    const float* W[4] = {Wi, Wf, Wc, Wo};
    int n = blockIdx.x * blockDim.x + threadIdx.x;
    int hi   = n & 1;
    int p    = (n >> 1) & 3;
    int pcol = (n >> 3) & 31;
    int k8   = (n >> 8) & 127;
    int bx   = n >> 15;
    int gate = pcol >> 3;
    int col  = bx * 8 + (pcol & 7);
    int k    = k8 * 8 + p + hi * 4;
    g_Wpk[n] = f2tf32(W[gate][(size_t)k * HH + col]);
}

// ---------------- big tf32 GEMM (unchanged) ----------------------------------
#define BM 128
#define BN 128
#define BKK 32

__device__ __forceinline__ void gemm_tf32_core(
    const float* __restrict__ A, const float* __restrict__ Bw,
    const float* __restrict__ bias, float* __restrict__ C)
{
    __shared__ __align__(16) float As[BM][BKK + 4];
    __shared__ __align__(16) float Bs[BKK][BN + 4];

    const int tid  = threadIdx.x;
    const int lane = tid & 31;
    const int w    = tid >> 5;
    const int wm   = w & 1;
    const int wn   = w >> 1;

    const int m0 = blockIdx.y * BM;
    const int n0 = blockIdx.x * BN;

    const int amr = tid >> 3;
    const int akc = (tid & 7) * 4;
    const int bkr = tid >> 5;
    const int bnc = (tid & 31) * 4;

    float acc[4][4][4];
    #pragma unroll
    for (int i = 0; i < 4; ++i)
        #pragma unroll
        for (int j = 0; j < 4; ++j)
            #pragma unroll
            for (int r = 0; r < 4; ++r) acc[i][j][r] = 0.0f;

    float4 pa[4], pb[4];
    #pragma unroll
    for (int i = 0; i < 4; ++i) {
        pa[i] = *(const float4*)(A  + (size_t)(m0 + amr + 32 * i) * II + akc);
        pb[i] = *(const float4*)(Bw + (size_t)(bkr + 8 * i) * HH + n0 + bnc);
    }
    #pragma unroll
    for (int i = 0; i < 4; ++i) {
        As[amr + 32 * i][akc + 0] = f2tf32(pa[i].x);
        As[amr + 32 * i][akc + 1] = f2tf32(pa[i].y);
        As[amr + 32 * i][akc + 2] = f2tf32(pa[i].z);
        As[amr + 32 * i][akc + 3] = f2tf32(pa[i].w);
        float4 t = pb[i];
        t.x = f2tf32(t.x); t.y = f2tf32(t.y); t.z = f2tf32(t.z); t.w = f2tf32(t.w);
        *(float4*)&Bs[bkr + 8 * i][bnc] = t;
    }
    __syncthreads();

    const int NT = II / BKK;
    for (int it = 0; it < NT; ++it) {
        const int knext = (it + 1) * BKK;
        if (knext < II) {
            #pragma unroll
            for (int i = 0; i < 4; ++i) {
                pa[i] = *(const float4*)(A  + (size_t)(m0 + amr + 32 * i) * II + knext + akc);
                pb[i] = *(const float4*)(Bw + (size_t)(knext + bkr + 8 * i) * HH + n0 + bnc);
            }
        }
        #pragma unroll
        for (int kk = 0; kk < 4; ++kk) {
            const int kb = kk * 8;
            uint32_t af[4][4], bf[4][2];
            #pragma unroll
            for (int mt = 0; mt < 4; ++mt) {
                int r = wm * 64 + mt * 16 + (lane >> 2);
                int c = kb + (lane & 3);
                af[mt][0] = __float_as_uint(As[r][c]);
                af[mt][1] = __float_as_uint(As[r + 8][c]);
                af[mt][2] = __float_as_uint(As[r][c + 4]);
                af[mt][3] = __float_as_uint(As[r + 8][c + 4]);
            }
            #pragma unroll
            for (int nt = 0; nt < 4; ++nt) {
                int n = wn * 32 + nt * 8 + (lane >> 2);
                bf[nt][0] = __float_as_uint(Bs[kb + (lane & 3)][n]);
                bf[nt][1] = __float_as_uint(Bs[kb + 4 + (lane & 3)][n]);
            }
            #pragma unroll
            for (int mt = 0; mt < 4; ++mt)
                #pragma unroll
                for (int nt = 0; nt < 4; ++nt)
                    mma_tf32(acc[mt][nt], af[mt], bf[nt]);
        }
        if (knext < II) {
            __syncthreads();
            #pragma unroll
            for (int i = 0; i < 4; ++i) {
                As[amr + 32 * i][akc + 0] = f2tf32(pa[i].x);
                As[amr + 32 * i][akc + 1] = f2tf32(pa[i].y);
                As[amr + 32 * i][akc + 2] = f2tf32(pa[i].z);
                As[amr + 32 * i][akc + 3] = f2tf32(pa[i].w);
                float4 t = pb[i];
                t.x = f2tf32(t.x); t.y = f2tf32(t.y); t.z = f2tf32(t.z); t.w = f2tf32(t.w);
                *(float4*)&Bs[bkr + 8 * i][bnc] = t;
            }
            __syncthreads();
        }
    }

    #pragma unroll
    for (int mt = 0; mt < 4; ++mt) {
        int row = m0 + wm * 64 + mt * 16 + (lane >> 2);
        #pragma unroll
        for (int nt = 0; nt < 4; ++nt) {
            int col = n0 + wn * 32 + nt * 8 + 2 * (lane & 3);
            float b0 = bias[col], b1 = bias[col + 1];
            float2 v0 = {acc[mt][nt][0] + b0, acc[mt][nt][1] + b1};
            float2 v1 = {acc[mt][nt][2] + b0, acc[mt][nt][3] + b1};
            *(float2*)&C[(size_t)row * HH + col]       = v0;
            *(float2*)&C[(size_t)(row + 8) * HH + col] = v1;
        }
    }
}

__global__ __launch_bounds__(256) void gemm_xproj(
    const float* __restrict__ x,
    const float* __restrict__ W0, const float* __restrict__ W1,
    const float* __restrict__ W2, const float* __restrict__ W3,
    const float* __restrict__ b0, const float* __restrict__ b1,
    const float* __restrict__ b2, const float* __restrict__ b3)
{
    const float* Ws[4] = {W0, W1, W2, W3};
    const float* bs[4] = {b0, b1, b2, b3};
    int g = blockIdx.z;
    gemm_tf32_core(x, Ws[g], bs[g], g_XP + (size_t)g * SB * HH);
}

__global__ __launch_bounds__(256) void gemm_outproj(
    const float* __restrict__ Why, const float* __restrict__ bhy,
    float* __restrict__ out)
{
    gemm_tf32_core(g_Hall, Why, bhy, out);
}

// ---------------- Persistent recurrence kernel -------------------------------
// 128 blocks x 512 threads (16 warps), 1 block/SM.
// Block bx owns hidden cols [bx*8, bx*8+8) x 4 gates = 32 pre-cols.
// Warp tiling: 8 k-groups (wk) x 2 m-halves (wmh). Each warp: m32 x n32,
// k8 indices == wk (mod 8). A frag reused over 4 n-tiles (no n-split).
// K-split reduced through smem (2 phases) aliasing the drained A buffers.
// smem: W 32768f | A 6*2048f (aliased by red[4][64][34]) | XP 2*2048f = 192KB
#define PSTAGES 6
#define PNIT 32
#define REDK 2176   // 64*34

__global__ __launch_bounds__(512) void lstm_persist(
    const float* __restrict__ bi, const float* __restrict__ bf,
    const float* __restrict__ bc, const float* __restrict__ bo)
{
    extern __shared__ __align__(16) float sm[];
    float* Wsm  = sm;                              // 32768
    float* Asm  = sm + 32768;                      // 6*2048 (also red)
    float* XPsm = Asm + PSTAGES * 2048;            // 2*2048

    const int tid  = threadIdx.x;
    const int lane = tid & 31;
    const int w    = tid >> 5;
    const int wk   = w & 7;        // k8 group (k8 == wk mod 8)
    const int wmh  = w >> 3;       // m half (rows wmh*32 .. +32)
    const int k8l  = wk & 3;       // k8 within a BK=32 stage
    const int kpar = wk >> 2;      // stage parity this warp works on
    const int bx   = blockIdx.x;
    const int c0   = bx * 8;

    const uint32_t sW = (uint32_t)__cvta_generic_to_shared(Wsm);
    const uint32_t sA = (uint32_t)__cvta_generic_to_shared(Asm);
    const uint32_t sX = (uint32_t)__cvta_generic_to_shared(XPsm);

    // ---- load weights once (32768 floats = 8192 x 16B) ----
    {
        const float* Wsrc = g_Wpk + (size_t)bx * 32768;
        #pragma unroll 4
        for (int j = 0; j < 16; ++j) {
            int idx = tid + 512 * j;
            cp_async16(sW + idx * 16, Wsrc + idx * 4);
        }
    }
    // ---- XP prefetch for step 0 ----
    {
        int gate = tid >> 7, r2 = (tid >> 1) & 63, half = tid & 1;
        const float* src = g_XP + (size_t)gate * SB * HH
                         + (size_t)r2 * HH + c0 + half * 4;
        cp_async16(sX + (gate * 512 + r2 * 8 + half * 4) * 4, src);
    }
    cp_commit();

    // per-thread epilogue constants
    const int cc  = tid & 7;
    const int col = c0 + cc;
    const int row = tid >> 3;            // 0..63
    const float bI = bi[col], bF = bf[col], bC = bc[col], bO = bo[col];
    float creg = 0.0f;

    for (int t = 0; t < SS; ++t) {
        const float* Asrc = g_HTp[t & 1];
        float*       hout = g_Hall + (size_t)t * BB * HH;
        float*       hTn  = g_HTp[(t + 1) & 1];

        float acc[2][4][4];   // [mt][nt][r]
        #pragma unroll
        for (int mt = 0; mt < 2; ++mt)
            #pragma unroll
            for (int nt = 0; nt < 4; ++nt)
                #pragma unroll
                for (int r = 0; r < 4; ++r) acc[mt][nt][r] = 0.0f;

        // prologue: A tiles 0..PSTAGES-2
        #pragma unroll
        for (int i = 0; i < PSTAGES - 1; ++i) {
            cp_async16(sA + ((i % PSTAGES) * 2048 + tid * 4) * 4,
                       Asrc + i * 2048 + tid * 4);
            cp_commit();
        }

        for (int it = 0; it < PNIT; ++it) {
            cp_wait<PSTAGES - 2>();
            __syncthreads();
            if (it + PSTAGES - 1 < PNIT) {
                int i = it + PSTAGES - 1;
                cp_async16(sA + ((i % PSTAGES) * 2048 + tid * 4) * 4,
                           Asrc + i * 2048 + tid * 4);
            }
            if (it == 0 && t + 1 < SS) {
                int buf  = (t + 1) & 1;
                int gate = tid >> 7, r2 = (tid >> 1) & 63, half = tid & 1;
                const float* src = g_XP + (size_t)gate * SB * HH
                                 + ((size_t)(t + 1) * BB + r2) * HH + c0 + half * 4;
                cp_async16(sX + (buf * 2048 + gate * 512 + r2 * 8 + half * 4) * 4, src);
            }
            cp_commit();

            if ((it & 1) == kpar) {
                const float* Asl = Asm + (it % PSTAGES) * 2048;
                const float* Bsl = Wsm + it * 1024;

                uint32_t af[2][4];
                #pragma unroll
                for (int mt = 0; mt < 2; ++mt) {
                    int base = k8l * 512 + (wmh * 32 + mt * 16 + (lane >> 2)) * 8 + (lane & 3) * 2;
                    float2 a0 = *(const float2*)(Asl + base);
                    float2 a1 = *(const float2*)(Asl + base + 64);
                    af[mt][0] = __float_as_uint(a0.x);
                    af[mt][1] = __float_as_uint(a1.x);
                    af[mt][2] = __float_as_uint(a0.y);
                    af[mt][3] = __float_as_uint(a1.y);
                }
                #pragma unroll
                for (int nt = 0; nt < 4; ++nt) {
                    int pb = k8l * 256 + (nt * 8 + (lane >> 2)) * 8 + (lane & 3) * 2;
                    float2 b = *(const float2*)(Bsl + pb);
                    uint32_t bfr[2] = {__float_as_uint(b.x), __float_as_uint(b.y)};
                    mma_tf32(acc[0][nt], af[0], bfr);
                    mma_tf32(acc[1][nt], af[1], bfr);
                }
            }
        }

        cp_wait<0>();
        __syncthreads();

        // ---- k-split reduction (red aliases Asm) ----
        float* red = Asm;   // red[4][64][34]
        // phase A: upper k-groups store
        if (kpar == 1) {
            #pragma unroll
            for (int mt = 0; mt < 2; ++mt)
                #pragma unroll
                for (int nt = 0; nt < 4; ++nt) {
                    int r0 = wmh * 32 + mt * 16 + (lane >> 2);
                    int cr = nt * 8 + 2 * (lane & 3);
                    *(float2*)&red[(k8l * 64 + r0) * 34 + cr]
                        = make_float2(acc[mt][nt][0], acc[mt][nt][1]);
                    *(float2*)&red[(k8l * 64 + r0 + 8) * 34 + cr]
                        = make_float2(acc[mt][nt][2], acc[mt][nt][3]);
                }
        }
        __syncthreads();
        // phase B: lower k-groups accumulate
        if (kpar == 0) {
            #pragma unroll
            for (int mt = 0; mt < 2; ++mt)
                #pragma unroll
                for (int nt = 0; nt < 4; ++nt) {
                    int r0 = wmh * 32 + mt * 16 + (lane >> 2);
                    int cr = nt * 8 + 2 * (lane & 3);
                    float2* p0 = (float2*)&red[(k8l * 64 + r0) * 34 + cr];
                    float2* p1 = (float2*)&red[(k8l * 64 + r0 + 8) * 34 + cr];
                    float2 u0 = *p0, u1 = *p1;
                    u0.x += acc[mt][nt][0]; u0.y += acc[mt][nt][1];
                    u1.x += acc[mt][nt][2]; u1.y += acc[mt][nt][3];
                    *p0 = u0; *p1 = u1;
                }
        }
        __syncthreads();

        // ---- fused elementwise epilogue: 1 element/thread ----
        const float* xp = XPsm + (t & 1) * 2048;
        {
            size_t off = (size_t)row * HH + col;
            int b0 = row * 34 + cc;

            float pi = red[b0]      + red[REDK + b0]      + red[2*REDK + b0]      + red[3*REDK + b0]
                     + xp[0 * 512 + row * 8 + cc] + bI;
            float pf = red[b0 + 8]  + red[REDK + b0 + 8]  + red[2*REDK + b0 + 8]  + red[3*REDK + b0 + 8]
                     + xp[1 * 512 + row * 8 + cc] + bF;
            float pc = red[b0 + 16] + red[REDK + b0 + 16] + red[2*REDK + b0 + 16] + red[3*REDK + b0 + 16]
                     + xp[2 * 512 + row * 8 + cc] + bC;
            float po = red[b0 + 24] + red[REDK + b0 + 24] + red[2*REDK + b0 + 24] + red[3*REDK + b0 + 24]
                     + xp[3 * 512 + row * 8 + cc] + bO;

            float iv = 1.0f / (1.0f + expf(-pi));
            float fv = 1.0f / (1.0f + expf(-pf));
            float ov = 1.0f / (1.0f + expf(-po));
            float gv = tanhf(pc);

            float cv = fv * creg + iv * gv;
            float hv = ov * tanhf(cv);
            creg = cv;

            hout[off] = hv;
            hTn[((bx * 64 + row) << 3) + ((col & 3) << 1) + ((col >> 2) & 1)] = f2tf32(hv);
        }

        // ---- grid barrier ----
        if (t + 1 < SS) {
            __threadfence();
            __syncthreads();
            if (tid == 0) {
                atomicAdd(&g_bar, 1u);
                unsigned need = 128u * (unsigned)(t + 1);
                while (*((volatile unsigned*)&g_bar) < need) { __nanosleep(16); }
            }
            __syncthreads();
        }
    }
}

// ---------------- launch -----------------------------------------------------
extern "C" void kernel_launch(void* const* d_in, const int* in_sizes, int n_in,
                              void* d_out, int out_size)
{
    (void)in_sizes; (void)n_in; (void)out_size;

    const float* x    = (const float*)d_in[0];
    const float* Wx[4] = {(const float*)d_in[1], (const float*)d_in[3],
                          (const float*)d_in[5], (const float*)d_in[7]};
    const float* bx[4] = {(const float*)d_in[2], (const float*)d_in[4],
                          (const float*)d_in[6], (const float*)d_in[8]};
    const float* Wh[4] = {(const float*)d_in[9],  (const float*)d_in[11],
                          (const float*)d_in[13], (const float*)d_in[15]};
    const float* bh[4] = {(const float*)d_in[10], (const float*)d_in[12],
                          (const float*)d_in[14], (const float*)d_in[16]};
    const float* Why = (const float*)d_in[17];
    const float* bhy = (const float*)d_in[18];
    float* out = (float*)d_out;

    static int smem_set = 0;
    const int psmem = (32768 + PSTAGES * 2048 + 2 * 2048) * 4;
    if (!smem_set) {
        cudaFuncSetAttribute(lstm_persist,
                             cudaFuncAttributeMaxDynamicSharedMemorySize, psmem);
        smem_set = 1;
    }

    init_state_kernel<<<(BB * HH + 255) / 256, 256>>>();
    repack_w<<<(128 * 128 * 32 * 8) / 256, 256>>>(Wh[0], Wh[1], Wh[2], Wh[3]);

    {
        dim3 grid(HH / BN, SB / BM, 4);
        gemm_xproj<<<grid, 256>>>(x, Wx[0], Wx[1], Wx[2], Wx[3],
                                     bx[0], bx[1], bx[2], bx[3]);
    }

    lstm_persist<<<128, 512, psmem>>>(bh[0], bh[1], bh[2], bh[3]);

    {
        dim3 grid(HH / BN, SB / BM);
        gemm_outproj<<<grid, 256>>>(Why, bhy, out);
    }
}

// round 10
// speedup vs baseline: 1.4876x; 1.4876x over previous
#include <cuda_runtime.h>
#include <math.h>
#include <stdint.h>

#define SS 512
#define BB 64
#define II 1024
#define HH 1024
#define SB (SS*BB)

// ---------------- scratch (static device globals; no allocation) -------------
__device__ float g_XP[4ULL * SB * HH];          // input projections [4][S*B][H]
__device__ float g_Hall[(size_t)SB * HH];       // h_t row-major (tf32-rounded)
__device__ float g_HTp[2][HH * BB];             // h transposed+pair-packed, ping-pong
__device__ float g_Wpk[128ULL * 128 * 32 * 8];  // packed recurrent weights
__device__ float g_Xr[(size_t)SB * II];         // tf32-rounded x
__device__ float g_Wxr[4ULL * II * HH];         // tf32-rounded input weights
__device__ float g_Whyr[(size_t)HH * HH];       // tf32-rounded output weights
__device__ unsigned g_bar;                       // grid barrier (monotonic)

// ---------------- helpers ----------------------------------------------------
__device__ __forceinline__ float f2tf32(float f) {
    uint32_t r;
    asm("cvt.rna.tf32.f32 %0, %1;" : "=r"(r) : "f"(f));
    return __uint_as_float(r);
}

__device__ __forceinline__ void mma_tf32(float c[4], const uint32_t a[4], const uint32_t b[2]) {
    asm volatile(
        "mma.sync.aligned.m16n8k8.row.col.f32.tf32.tf32.f32 "
        "{%0,%1,%2,%3}, {%4,%5,%6,%7}, {%8,%9}, {%0,%1,%2,%3};"
        : "+f"(c[0]), "+f"(c[1]), "+f"(c[2]), "+f"(c[3])
        : "r"(a[0]), "r"(a[1]), "r"(a[2]), "r"(a[3]), "r"(b[0]), "r"(b[1]));
}

__device__ __forceinline__ void cp_async16(uint32_t dst_smem, const void* src) {
    asm volatile("cp.async.cg.shared.global [%0], [%1], 16;" :: "r"(dst_smem), "l"(src));
}
__device__ __forceinline__ void cp_commit() { asm volatile("cp.async.commit_group;"); }
template<int N> __device__ __forceinline__ void cp_wait() {
    asm volatile("cp.async.wait_group %0;" :: "n"(N));
}

// ---------------- init / repack ----------------------------------------------
__global__ void init_state_kernel() {
    int idx = blockIdx.x * blockDim.x + threadIdx.x;
    if (idx < BB * HH) g_HTp[0][idx] = 0.0f;
    if (idx == 0) g_bar = 0u;
}

__global__ __launch_bounds__(256) void repack_w(
    const float* __restrict__ Wi, const float* __restrict__ Wf,
    const float* __restrict__ Wc, const float* __restrict__ Wo)
{
    const float* W[4] = {Wi, Wf, Wc, Wo};
    int n = blockIdx.x * blockDim.x + threadIdx.x;
    int hi   = n & 1;
    int p    = (n >> 1) & 3;
    int pcol = (n >> 3) & 31;
    int k8   = (n >> 8) & 127;
    int bx   = n >> 15;
    int gate = pcol >> 3;
    int col  = bx * 8 + (pcol & 7);
    int k    = k8 * 8 + p + hi * 4;
    g_Wpk[n] = f2tf32(W[gate][(size_t)k * HH + col]);
}

__global__ __launch_bounds__(256) void round_x(const float* __restrict__ x) {
    size_t i = (size_t)blockIdx.x * 256 + threadIdx.x;
    g_Xr[i] = f2tf32(x[i]);
}
__global__ __launch_bounds__(256) void round_wx(
    const float* __restrict__ W0, const float* __restrict__ W1,
    const float* __restrict__ W2, const float* __restrict__ W3)
{
    const float* W[4] = {W0, W1, W2, W3};
    size_t i = (size_t)blockIdx.x * 256 + threadIdx.x;
    int g = (int)(i >> 20);
    g_Wxr[i] = f2tf32(W[g][i & 0xFFFFF]);
}
__global__ __launch_bounds__(256) void round_why(const float* __restrict__ Why) {
    size_t i = (size_t)blockIdx.x * 256 + threadIdx.x;
    g_Whyr[i] = f2tf32(Why[i]);
}

// ---------------- big tf32 GEMM, cp.async 3-stage ----------------------------
// C[M,1024] = A[M,1024] @ B[1024,1024] + bias. A,B pre-rounded to tf32.
// 128x128 tile, BK=32, 256 threads (8 warps: 2m x 4n), 3 stages.
// NOTE: called only from __global__ wrappers that bind device globals in
// DEVICE code (passing __device__ globals from host is UB and was the R8/R9 bug).
#define GAS 4608   // A stage: 128*36
#define GBS 4224   // B stage: 32*132
#define GST 3

__device__ __forceinline__ void gemm_async_core(
    const float* __restrict__ A, const float* __restrict__ Bw,
    const float* __restrict__ bias, float* __restrict__ C)
{
    extern __shared__ __align__(16) float gsm[];
    float* Asm = gsm;                 // 3 * 4608
    float* Bsm = gsm + GST * GAS;     // 3 * 4224

    const int tid  = threadIdx.x;
    const int lane = tid & 31;
    const int w    = tid >> 5;
    const int wm   = w & 1;
    const int wn   = w >> 1;
    const int m0   = blockIdx.y * 128;
    const int n0   = blockIdx.x * 128;

    const uint32_t sA = (uint32_t)__cvta_generic_to_shared(Asm);
    const uint32_t sB = (uint32_t)__cvta_generic_to_shared(Bsm);

    float acc[4][4][4];
    #pragma unroll
    for (int i = 0; i < 4; ++i)
        #pragma unroll
        for (int j = 0; j < 4; ++j)
            #pragma unroll
            for (int r = 0; r < 4; ++r) acc[i][j][r] = 0.0f;

    auto issue = [&](int it, int slot) {
        int k0 = it * 32;
        #pragma unroll
        for (int j = 0; j < 4; ++j) {
            int idx = tid + 256 * j;          // 0..1023
            int ar = idx >> 3, akc = (idx & 7) * 4;
            cp_async16(sA + (slot * GAS + ar * 36 + akc) * 4,
                       A + (size_t)(m0 + ar) * II + k0 + akc);
            int bk = idx >> 5, bnc = (idx & 31) * 4;
            cp_async16(sB + (slot * GBS + bk * 132 + bnc) * 4,
                       Bw + (size_t)(k0 + bk) * HH + n0 + bnc);
        }
    };

    issue(0, 0); cp_commit();
    issue(1, 1); cp_commit();

    for (int it = 0; it < 32; ++it) {
        cp_wait<1>();
        __syncthreads();
        if (it + 2 < 32) issue(it + 2, (it + 2) % GST);
        cp_commit();

        const float* As = Asm + (it % GST) * GAS;
        const float* Bs = Bsm + (it % GST) * GBS;

        #pragma unroll
        for (int kk = 0; kk < 4; ++kk) {
            const int kb = kk * 8;
            uint32_t af[4][4], bf[4][2];
            #pragma unroll
            for (int mt = 0; mt < 4; ++mt) {
                int r = wm * 64 + mt * 16 + (lane >> 2);
                int c = kb + (lane & 3);
                af[mt][0] = __float_as_uint(As[r * 36 + c]);
                af[mt][1] = __float_as_uint(As[(r + 8) * 36 + c]);
                af[mt][2] = __float_as_uint(As[r * 36 + c + 4]);
                af[mt][3] = __float_as_uint(As[(r + 8) * 36 + c + 4]);
            }
            #pragma unroll
            for (int nt = 0; nt < 4; ++nt) {
                int n = wn * 32 + nt * 8 + (lane >> 2);
                bf[nt][0] = __float_as_uint(Bs[(kb + (lane & 3)) * 132 + n]);
                bf[nt][1] = __float_as_uint(Bs[(kb + 4 + (lane & 3)) * 132 + n]);
            }
            #pragma unroll
            for (int mt = 0; mt < 4; ++mt)
                #pragma unroll
                for (int nt = 0; nt < 4; ++nt)
                    mma_tf32(acc[mt][nt], af[mt], bf[nt]);
        }
    }

    #pragma unroll
    for (int mt = 0; mt < 4; ++mt) {
        int row = m0 + wm * 64 + mt * 16 + (lane >> 2);
        #pragma unroll
        for (int nt = 0; nt < 4; ++nt) {
            int col = n0 + wn * 32 + nt * 8 + 2 * (lane & 3);
            float b0 = bias[col], b1 = bias[col + 1];
            float2 v0 = {acc[mt][nt][0] + b0, acc[mt][nt][1] + b1};
            float2 v1 = {acc[mt][nt][2] + b0, acc[mt][nt][3] + b1};
            *(float2*)&C[(size_t)row * HH + col]       = v0;
            *(float2*)&C[(size_t)(row + 8) * HH + col] = v1;
        }
    }
}

// Wrappers: device globals bound in DEVICE code; only harness pointers as args.
__global__ __launch_bounds__(256) void gemm_xproj_async(
    const float* __restrict__ bias, int g)
{
    gemm_async_core(g_Xr, g_Wxr + (size_t)g * II * HH, bias,
                    g_XP + (size_t)g * SB * HH);
}

__global__ __launch_bounds__(256) void gemm_outproj_async(
    const float* __restrict__ bias, float* __restrict__ out)
{
    gemm_async_core(g_Hall, g_Whyr, bias, out);
}

// ---------------- Persistent recurrence kernel -------------------------------
// 128 blocks x 512 threads (16 warps), 1 block/SM.
// Block bx: hidden cols [bx*8,bx*8+8) x 4 gates = 32 pre-cols, 64 batch rows.
// Warps: 4 m-tiles (wm) x 4 k8-subblocks (wk) WITHIN each BK=32 stage
// => every warp active every iteration. 4-way k-reduction through smem
// (aliases drained A stages; stride 34 keeps float2 8B-aligned).
#define PSTAGES 6
#define PNIT 32
#define REDW 2176   // 64*34

__global__ __launch_bounds__(512) void lstm_persist(
    const float* __restrict__ bi, const float* __restrict__ bf,
    const float* __restrict__ bc, const float* __restrict__ bo)
{
    extern __shared__ __align__(16) float sm[];
    float* Wsm  = sm;                              // 32768
    float* Asm  = sm + 32768;                      // 6*2048 (alias red 3*2176)
    float* XPsm = Asm + PSTAGES * 2048;            // 2*2048
    float* pre  = XPsm + 4096;                     // 2176

    const int tid  = threadIdx.x;
    const int lane = tid & 31;
    const int w    = tid >> 5;
    const int wm   = w & 3;        // m-tile (16 rows)
    const int wk   = w >> 2;       // k8 subblock within stage
    const int bx   = blockIdx.x;
    const int c0   = bx * 8;

    const uint32_t sW = (uint32_t)__cvta_generic_to_shared(Wsm);
    const uint32_t sA = (uint32_t)__cvta_generic_to_shared(Asm);
    const uint32_t sX = (uint32_t)__cvta_generic_to_shared(XPsm);

    // ---- load weights once ----
    {
        const float* Wsrc = g_Wpk + (size_t)bx * 32768;
        #pragma unroll 4
        for (int j = 0; j < 16; ++j) {
            int idx = tid + 512 * j;
            cp_async16(sW + idx * 16, Wsrc + idx * 4);
        }
    }
    // ---- XP prefetch for step 0 ----
    {
        int gate = tid >> 7, r2 = (tid >> 1) & 63, half = tid & 1;
        const float* src = g_XP + (size_t)gate * SB * HH
                         + (size_t)r2 * HH + c0 + half * 4;
        cp_async16(sX + (gate * 512 + r2 * 8 + half * 4) * 4, src);
    }
    cp_commit();

    // per-thread epilogue constants
    const int cc  = tid & 7;
    const int col = c0 + cc;
    const int row = tid >> 3;            // 0..63
    const float bI = bi[col], bF = bf[col], bC = bc[col], bO = bo[col];
    float creg = 0.0f;

    for (int t = 0; t < SS; ++t) {
        const float* Asrc = g_HTp[t & 1];
        float*       hout = g_Hall + (size_t)t * BB * HH;
        float*       hTn  = g_HTp[(t + 1) & 1];

        float acc[4][4];     // [nt][r], partial over k8==wk of each stage
        #pragma unroll
        for (int nt = 0; nt < 4; ++nt)
            #pragma unroll
            for (int r = 0; r < 4; ++r) acc[nt][r] = 0.0f;

        // prologue
        #pragma unroll
        for (int i = 0; i < PSTAGES - 1; ++i) {
            cp_async16(sA + ((i % PSTAGES) * 2048 + tid * 4) * 4,
                       Asrc + i * 2048 + tid * 4);
            cp_commit();
        }

        for (int it = 0; it < PNIT; ++it) {
            cp_wait<PSTAGES - 2>();
            __syncthreads();
            if (it + PSTAGES - 1 < PNIT) {
                int i = it + PSTAGES - 1;
                cp_async16(sA + ((i % PSTAGES) * 2048 + tid * 4) * 4,
                           Asrc + i * 2048 + tid * 4);
            }
            if (it == 0 && t + 1 < SS) {
                int buf  = (t + 1) & 1;
                int gate = tid >> 7, r2 = (tid >> 1) & 63, half = tid & 1;
                const float* src = g_XP + (size_t)gate * SB * HH
                                 + ((size_t)(t + 1) * BB + r2) * HH + c0 + half * 4;
                cp_async16(sX + (buf * 2048 + gate * 512 + r2 * 8 + half * 4) * 4, src);
            }
            cp_commit();

            const float* Asl = Asm + (it % PSTAGES) * 2048;
            const float* Bsl = Wsm + it * 1024;

            uint32_t af[4];
            {
                int base = wk * 512 + (wm * 16 + (lane >> 2)) * 8 + (lane & 3) * 2;
                float2 a0 = *(const float2*)(Asl + base);
                float2 a1 = *(const float2*)(Asl + base + 64);
                af[0] = __float_as_uint(a0.x);
                af[1] = __float_as_uint(a1.x);
                af[2] = __float_as_uint(a0.y);
                af[3] = __float_as_uint(a1.y);
            }
            #pragma unroll
            for (int nt = 0; nt < 4; ++nt) {
                int pb = wk * 256 + (nt * 8 + (lane >> 2)) * 8 + (lane & 3) * 2;
                float2 b = *(const float2*)(Bsl + pb);
                uint32_t bfr[2] = {__float_as_uint(b.x), __float_as_uint(b.y)};
                mma_tf32(acc[nt], af, bfr);
            }
        }

        cp_wait<0>();
        __syncthreads();

        // ---- 4-way k reduction (red aliases Asm) ----
        float* red = Asm;   // red[3][64][34]
        if (wk > 0) {
            #pragma unroll
            for (int nt = 0; nt < 4; ++nt) {
                int r0 = wm * 16 + (lane >> 2);
                int cr = nt * 8 + 2 * (lane & 3);
                *(float2*)&red[(wk - 1) * REDW + r0 * 34 + cr]
                    = make_float2(acc[nt][0], acc[nt][1]);
                *(float2*)&red[(wk - 1) * REDW + (r0 + 8) * 34 + cr]
                    = make_float2(acc[nt][2], acc[nt][3]);
            }
        }
        __syncthreads();
        if (wk == 0) {
            #pragma unroll
            for (int nt = 0; nt < 4; ++nt) {
                int r0 = wm * 16 + (lane >> 2);
                int cr = nt * 8 + 2 * (lane & 3);
                float2 s0 = make_float2(acc[nt][0], acc[nt][1]);
                float2 s1 = make_float2(acc[nt][2], acc[nt][3]);
                #pragma unroll
                for (int p = 0; p < 3; ++p) {
                    float2 u0 = *(const float2*)&red[p * REDW + r0 * 34 + cr];
                    float2 u1 = *(const float2*)&red[p * REDW + (r0 + 8) * 34 + cr];
                    s0.x += u0.x; s0.y += u0.y;
                    s1.x += u1.x; s1.y += u1.y;
                }
                *(float2*)&pre[r0 * 34 + cr]       = s0;
                *(float2*)&pre[(r0 + 8) * 34 + cr] = s1;
            }
        }
        __syncthreads();

        // ---- fused elementwise epilogue: 1 element/thread ----
        const float* xp = XPsm + (t & 1) * 2048;
        {
            size_t off = (size_t)row * HH + col;
            int b0 = row * 34 + cc;

            float pi = pre[b0]      + xp[0 * 512 + row * 8 + cc] + bI;
            float pf = pre[b0 + 8]  + xp[1 * 512 + row * 8 + cc] + bF;
            float pc = pre[b0 + 16] + xp[2 * 512 + row * 8 + cc] + bC;
            float po = pre[b0 + 24] + xp[3 * 512 + row * 8 + cc] + bO;

            float iv = 1.0f / (1.0f + expf(-pi));
            float fv = 1.0f / (1.0f + expf(-pf));
            float ov = 1.0f / (1.0f + expf(-po));
            float gv = tanhf(pc);

            float cv = fv * creg + iv * gv;
            float hv = ov * tanhf(cv);
            creg = cv;

            float hr = f2tf32(hv);
            hout[off] = hr;   // tf32-rounded: outproj consumes pre-rounded A
            hTn[((bx * 64 + row) << 3) + ((col & 3) << 1) + ((col >> 2) & 1)] = hr;
        }

        // ---- grid barrier ----
        if (t + 1 < SS) {
            __threadfence();
            __syncthreads();
            if (tid == 0) {
                atomicAdd(&g_bar, 1u);
                unsigned need = 128u * (unsigned)(t + 1);
                while (*((volatile unsigned*)&g_bar) < need) { __nanosleep(16); }
            }
            __syncthreads();
        }
    }
}

// ---------------- launch -----------------------------------------------------
extern "C" void kernel_launch(void* const* d_in, const int* in_sizes, int n_in,
                              void* d_out, int out_size)
{
    (void)in_sizes; (void)n_in; (void)out_size;

    const float* x    = (const float*)d_in[0];
    const float* Wx[4] = {(const float*)d_in[1], (const float*)d_in[3],
                          (const float*)d_in[5], (const float*)d_in[7]};
    const float* bx[4] = {(const float*)d_in[2], (const float*)d_in[4],
                          (const float*)d_in[6], (const float*)d_in[8]};
    const float* Wh[4] = {(const float*)d_in[9],  (const float*)d_in[11],
                          (const float*)d_in[13], (const float*)d_in[15]};
    const float* bh[4] = {(const float*)d_in[10], (const float*)d_in[12],
                          (const float*)d_in[14], (const float*)d_in[16]};
    const float* Why = (const float*)d_in[17];
    const float* bhy = (const float*)d_in[18];
    float* out = (float*)d_out;

    static int smem_set = 0;
    const int psmem = (32768 + PSTAGES * 2048 + 2 * 2048 + REDW) * 4;
    const int gsmem = GST * (GAS + GBS) * 4;
    if (!smem_set) {
        cudaFuncSetAttribute(lstm_persist,
                             cudaFuncAttributeMaxDynamicSharedMemorySize, psmem);
        cudaFuncSetAttribute(gemm_xproj_async,
                             cudaFuncAttributeMaxDynamicSharedMemorySize, gsmem);
        cudaFuncSetAttribute(gemm_outproj_async,
                             cudaFuncAttributeMaxDynamicSharedMemorySize, gsmem);
        smem_set = 1;
    }

    init_state_kernel<<<(BB * HH + 255) / 256, 256>>>();
    repack_w<<<(128 * 128 * 32 * 8) / 256, 256>>>(Wh[0], Wh[1], Wh[2], Wh[3]);
    round_x<<<(int)(((size_t)SB * II) / 256), 256>>>(x);
    round_wx<<<(4 * II * HH) / 256, 256>>>(Wx[0], Wx[1], Wx[2], Wx[3]);
    round_why<<<(II * HH) / 256, 256>>>(Why);

    // input projections: XP[g] = x @ W_x[g] + b_x[g]
    {
        dim3 grid(HH / 128, SB / 128);
        for (int g = 0; g < 4; ++g)
            gemm_xproj_async<<<grid, 256, gsmem>>>(bx[g], g);
    }

    lstm_persist<<<128, 512, psmem>>>(bh[0], bh[1], bh[2], bh[3]);

    // output projection: Y = H_all @ W_hy + b_hy
    {
        dim3 grid(HH / 128, SB / 128);
        gemm_outproj_async<<<grid, 256, gsmem>>>(bhy, out);
    }
}